// round 4
// baseline (speedup 1.0000x reference)
#include <cuda_runtime.h>
#include <math.h>

#define HEAD 64
#define NEMB 1024
#define BATCH 8
#define SEQ   2048
#define MTOT  (BATCH*SEQ)   // 16384
#define NTB   (SEQ/64)      // 32 t-blocks per batch

// scratch for projected k,q,v : [3][16384][64] fp32 = 12.6 MB
__device__ float g_kqv[3][MTOT][HEAD];

// ---------------------------------------------------------------------------
// Projection: g_kqv[p] = x @ W[p] + b[p]
// BM=64, BN=64(=HEAD), BK=32 tiles, 256 threads, 4x4 micro-tile per thread.
// ---------------------------------------------------------------------------
__global__ __launch_bounds__(256) void proj_kernel(
    const float* __restrict__ x,
    const float* __restrict__ Wk, const float* __restrict__ bk,
    const float* __restrict__ Wq, const float* __restrict__ bq,
    const float* __restrict__ Wv, const float* __restrict__ bv)
{
    const int p = blockIdx.y;
    const float* __restrict__ W    = (p == 0) ? Wk : ((p == 1) ? Wq : Wv);
    const float* __restrict__ bias = (p == 0) ? bk : ((p == 1) ? bq : bv);
    const int m0 = blockIdx.x * 64;

    __shared__ float xs[32][64];   // [k][m]  (transposed x tile)
    __shared__ float ws[32][64];   // [k][n]

    const int tid = threadIdx.x;
    const int tx  = tid & 15;      // n-dir (4 cols each)
    const int ty  = tid >> 4;      // m-dir (4 rows each)
    const int lm  = tid & 63;      // load row
    const int lk  = (tid >> 6) * 4;

    float acc[4][4] = {};

    for (int k0 = 0; k0 < NEMB; k0 += 32) {
        // x tile: load float4 along k, scatter transposed (conflict-free: warp = consecutive m)
        #pragma unroll
        for (int r = 0; r < 2; ++r) {
            int kk = lk + r * 16;
            float4 v = *(const float4*)&x[(size_t)(m0 + lm) * NEMB + (k0 + kk)];
            xs[kk+0][lm] = v.x; xs[kk+1][lm] = v.y; xs[kk+2][lm] = v.z; xs[kk+3][lm] = v.w;
        }
        // W tile: straight float4 copy
        #pragma unroll
        for (int r = 0; r < 2; ++r) {
            int idx = tid + r * 256;          // float4 index (512 total)
            int kk = idx >> 4, nn = (idx & 15) * 4;
            *(float4*)&ws[kk][nn] = *(const float4*)&W[(size_t)(k0 + kk) * HEAD + nn];
        }
        __syncthreads();

        #pragma unroll 8
        for (int k = 0; k < 32; ++k) {
            float4 a4 = *(const float4*)&xs[k][ty * 4];
            float4 b4 = *(const float4*)&ws[k][tx * 4];
            float av[4]  = {a4.x, a4.y, a4.z, a4.w};
            float bv4[4] = {b4.x, b4.y, b4.z, b4.w};
            #pragma unroll
            for (int i = 0; i < 4; ++i)
                #pragma unroll
                for (int j = 0; j < 4; ++j)
                    acc[i][j] = fmaf(av[i], bv4[j], acc[i][j]);
        }
        __syncthreads();
    }

    float bb[4];
    #pragma unroll
    for (int j = 0; j < 4; ++j) bb[j] = bias[tx * 4 + j];
    #pragma unroll
    for (int i = 0; i < 4; ++i) {
        float4 o;
        o.x = acc[i][0] + bb[0]; o.y = acc[i][1] + bb[1];
        o.z = acc[i][2] + bb[2]; o.w = acc[i][3] + bb[3];
        *(float4*)&g_kqv[p][m0 + ty * 4 + i][tx * 4] = o;
    }
}

// ---------------------------------------------------------------------------
// Attention: O[t] = sum_{s<=t} softplus( (k_t . q_s) / 32 ) * v_s
// 64x64 tiles. CTA handles t-blocks {i, 31-i} -> exactly 33 s-iters per CTA.
// Grid (16, 8) = 128 CTAs, single wave.
// ---------------------------------------------------------------------------
__device__ __forceinline__ float softplus_f(float x) {
    return fmaxf(x, 0.f) + __logf(1.f + __expf(-fabsf(x)));
}

__global__ __launch_bounds__(256) void attn_kernel(float* __restrict__ out)
{
    __shared__ float ks [64][64];   // [h][t]   (K tile transposed)
    __shared__ float vs [64][64];   // [s][h]
    __shared__ float qss[64][64];   // union: qs [h][s] then Ssm [t][s]

    const int b   = blockIdx.y;
    const int tid = threadIdx.x;
    const int tx  = tid & 15;       // s-dir (S phase) / h-dir (PV phase)
    const int ty  = tid >> 4;       // t-dir
    const int lr  = tid & 63;
    const int lh  = (tid >> 6) * 4;

    const float* __restrict__ Kg = &g_kqv[0][(size_t)b * SEQ][0];
    const float* __restrict__ Qg = &g_kqv[1][(size_t)b * SEQ][0];
    const float* __restrict__ Vg = &g_kqv[2][(size_t)b * SEQ][0];

    for (int half = 0; half < 2; ++half) {
        const int tb = half ? (NTB - 1 - (int)blockIdx.x) : (int)blockIdx.x;

        // load K tile (transposed)
        #pragma unroll
        for (int r = 0; r < 4; ++r) {
            int hh = lh + r * 16;
            float4 v = *(const float4*)&Kg[(size_t)(tb * 64 + lr) * HEAD + hh];
            ks[hh+0][lr] = v.x; ks[hh+1][lr] = v.y; ks[hh+2][lr] = v.z; ks[hh+3][lr] = v.w;
        }
        float O[4][4] = {};

        for (int sb = 0; sb <= tb; ++sb) {
            // Q tile transposed into qss, V tile direct into vs
            #pragma unroll
            for (int r = 0; r < 4; ++r) {
                int hh = lh + r * 16;
                float4 v = *(const float4*)&Qg[(size_t)(sb * 64 + lr) * HEAD + hh];
                qss[hh+0][lr] = v.x; qss[hh+1][lr] = v.y; qss[hh+2][lr] = v.z; qss[hh+3][lr] = v.w;
            }
            #pragma unroll
            for (int r = 0; r < 4; ++r) {
                int idx = tid + r * 256;
                int ss = idx >> 4, hh = (idx & 15) * 4;
                *(float4*)&vs[ss][hh] = *(const float4*)&Vg[(size_t)(sb * 64 + ss) * HEAD + hh];
            }
            __syncthreads();

            // S = K_t . Q_s^T  (contraction over h)
            float S[4][4] = {};
            #pragma unroll 8
            for (int h = 0; h < 64; ++h) {
                float4 a4 = *(const float4*)&ks [h][ty * 4];
                float4 b4 = *(const float4*)&qss[h][tx * 4];
                float av[4]  = {a4.x, a4.y, a4.z, a4.w};
                float bv4[4] = {b4.x, b4.y, b4.z, b4.w};
                #pragma unroll
                for (int i = 0; i < 4; ++i)
                    #pragma unroll
                    for (int j = 0; j < 4; ++j)
                        S[i][j] = fmaf(av[i], bv4[j], S[i][j]);
            }
            __syncthreads();   // qss reads complete before overwrite

            // softplus + causal mask, store S in natural [t][s] layout (float4 rows)
            const bool diag = (sb == tb);
            #pragma unroll
            for (int i = 0; i < 4; ++i) {
                float4 w4;
                float* wp = &w4.x;
                #pragma unroll
                for (int j = 0; j < 4; ++j) {
                    float sp = softplus_f(S[i][j] * 0.03125f);
                    if (diag && (tx * 4 + j) > (ty * 4 + i)) sp = 0.f;
                    wp[j] = sp;
                }
                *(float4*)&qss[ty * 4 + i][tx * 4] = w4;
            }
            __syncthreads();

            // O += S @ V  (contraction over s); S rows via broadcast float4s
            #pragma unroll 4
            for (int s0 = 0; s0 < 64; s0 += 4) {
                float4 a[4], bb4[4];
                #pragma unroll
                for (int i = 0; i < 4; ++i)  a[i]  = *(const float4*)&qss[ty * 4 + i][s0];
                #pragma unroll
                for (int sj = 0; sj < 4; ++sj) bb4[sj] = *(const float4*)&vs[s0 + sj][tx * 4];
                #pragma unroll
                for (int i = 0; i < 4; ++i) {
                    const float as[4] = {a[i].x, a[i].y, a[i].z, a[i].w};
                    #pragma unroll
                    for (int sj = 0; sj < 4; ++sj) {
                        const float* bp = &bb4[sj].x;
                        #pragma unroll
                        for (int j = 0; j < 4; ++j)
                            O[i][j] = fmaf(as[sj], bp[j], O[i][j]);
                    }
                }
            }
            __syncthreads();   // before next iter overwrites qss/vs
        }

        // write O tile
        #pragma unroll
        for (int i = 0; i < 4; ++i) {
            float4 o = {O[i][0], O[i][1], O[i][2], O[i][3]};
            *(float4*)&out[((size_t)b * SEQ + tb * 64 + ty * 4 + i) * HEAD + tx * 4] = o;
        }
        __syncthreads();       // before next half overwrites ks
    }
}

// ---------------------------------------------------------------------------
extern "C" void kernel_launch(void* const* d_in, const int* in_sizes, int n_in,
                              void* d_out, int out_size)
{
    const float* x  = (const float*)d_in[0];
    const float* Wk = (const float*)d_in[1];
    const float* bk = (const float*)d_in[2];
    const float* Wq = (const float*)d_in[3];
    const float* bq = (const float*)d_in[4];
    const float* Wv = (const float*)d_in[5];
    const float* bv = (const float*)d_in[6];
    float* out = (float*)d_out;

    dim3 pg(MTOT / 64, 3);
    proj_kernel<<<pg, 256>>>(x, Wk, bk, Wq, bq, Wv, bv);

    dim3 ag(NTB / 2, BATCH);
    attn_kernel<<<ag, 256>>>(out);
}

// round 6
// speedup vs baseline: 2.6411x; 2.6411x over previous
#include <cuda_runtime.h>
#include <cstdint>
#include <math.h>

#define HEAD 64
#define NEMB 1024
#define BATCH 8
#define SEQ   2048
#define MTOT  (BATCH*SEQ)   // 16384
#define NTB   (SEQ/64)      // 32 t-blocks per batch

// scratch: projected k,q,v fp32 (12.6 MB) + transposed tf32-rounded weights
__device__ float g_kqv[3][MTOT][HEAD];
__device__ float g_Wt[3][HEAD][NEMB];   // Wt[p][n][k] = rna_tf32(W[p][k][n])

__device__ __forceinline__ float to_tf32(float x) {
    float y; asm("cvt.rna.tf32.f32 %0, %1;" : "=f"(y) : "f"(x)); return y;
}
__device__ __forceinline__ uint32_t to_tf32_bits(float x) {
    float y; asm("cvt.rna.tf32.f32 %0, %1;" : "=f"(y) : "f"(x));
    return __float_as_uint(y);
}

// D += A*B : m16n8k8 tf32 (A row-major frag, B col-major frag), fp32 accum
__device__ __forceinline__ void mma8(float c[4], const uint32_t a[4], uint32_t b0, uint32_t b1) {
    asm volatile(
        "mma.sync.aligned.m16n8k8.row.col.f32.tf32.tf32.f32 "
        "{%0,%1,%2,%3}, {%4,%5,%6,%7}, {%8,%9}, {%0,%1,%2,%3};"
        : "+f"(c[0]), "+f"(c[1]), "+f"(c[2]), "+f"(c[3])
        : "r"(a[0]), "r"(a[1]), "r"(a[2]), "r"(a[3]), "r"(b0), "r"(b1));
}

// ---------------------------------------------------------------------------
// W transpose + tf32 pre-round:  g_Wt[p][n][k] = rna(W[p][k][n])
// ---------------------------------------------------------------------------
__global__ __launch_bounds__(256) void wt_kernel(
    const float* __restrict__ Wk, const float* __restrict__ Wq, const float* __restrict__ Wv)
{
    const float* __restrict__ W = (blockIdx.y == 0) ? Wk : ((blockIdx.y == 1) ? Wq : Wv);
    const int k0 = blockIdx.x * 64;
    #pragma unroll
    for (int i = 0; i < 16; ++i) {
        int idx = i * 256 + threadIdx.x;     // 0..4095
        int kk = idx >> 6, n = idx & 63;
        g_Wt[blockIdx.y][n][k0 + kk] = to_tf32(W[(size_t)(k0 + kk) * HEAD + n]);
    }
}

// ---------------------------------------------------------------------------
// Projection via mma.sync tf32. CTA tile: 128(m) x 192(n=3x64), K chunk 32.
// 8 warps in 4(m) x 2(n) grid: each warp 32 rows x 96 cols.
// smem stride 36 floats (36 mod 32 = 4 -> conflict-free fragment loads).
// ---------------------------------------------------------------------------
__global__ __launch_bounds__(256, 1) void proj_mma_kernel(
    const float* __restrict__ x,
    const float* __restrict__ bk, const float* __restrict__ bq, const float* __restrict__ bv)
{
    __shared__ float xs[128][36];   // [m][k] tf32-rounded
    __shared__ float ws[192][36];   // [n_global][k] tf32-rounded

    const int tid  = threadIdx.x;
    const int wid  = tid >> 5, lane = tid & 31;
    const int wm   = wid >> 1, wn = wid & 1;
    const int g    = lane >> 2, t = lane & 3;
    const int m0   = blockIdx.x * 128;

    float c[2][12][4];
    #pragma unroll
    for (int mt = 0; mt < 2; ++mt)
        #pragma unroll
        for (int nt = 0; nt < 12; ++nt)
            #pragma unroll
            for (int r = 0; r < 4; ++r) c[mt][nt][r] = 0.f;

    for (int k0 = 0; k0 < NEMB; k0 += 32) {
        // x tile: 128x32 -> 1024 float4 loads, tf32-round
        #pragma unroll
        for (int i = 0; i < 4; ++i) {
            int idx = i * 256 + tid;
            int row = idx >> 3, kk = (idx & 7) * 4;
            float4 v = *(const float4*)&x[(size_t)(m0 + row) * NEMB + k0 + kk];
            float* d = &xs[row][kk];
            d[0] = to_tf32(v.x); d[1] = to_tf32(v.y); d[2] = to_tf32(v.z); d[3] = to_tf32(v.w);
        }
        // W tiles: 192x32 (already rounded)
        #pragma unroll
        for (int i = 0; i < 6; ++i) {
            int idx = i * 256 + tid;
            int row = idx >> 3, kk = (idx & 7) * 4;
            float4 v = *(const float4*)&g_Wt[row >> 6][row & 63][k0 + kk];
            *(float4*)&ws[row][kk] = v;
        }
        __syncthreads();

        // A fragments: 2 m-tiles x 4 k-tiles
        uint32_t A[2][4][4];
        #pragma unroll
        for (int mt = 0; mt < 2; ++mt) {
            const int row = wm * 32 + mt * 16 + g;
            #pragma unroll
            for (int kt = 0; kt < 4; ++kt) {
                const int col = kt * 8 + t;
                A[mt][kt][0] = __float_as_uint(xs[row    ][col    ]);
                A[mt][kt][1] = __float_as_uint(xs[row + 8][col    ]);
                A[mt][kt][2] = __float_as_uint(xs[row    ][col + 4]);
                A[mt][kt][3] = __float_as_uint(xs[row + 8][col + 4]);
            }
        }
        #pragma unroll
        for (int kt = 0; kt < 4; ++kt) {
            #pragma unroll
            for (int nt = 0; nt < 12; ++nt) {
                const int ng = wn * 96 + nt * 8 + g;
                const int col = kt * 8 + t;
                uint32_t b0 = __float_as_uint(ws[ng][col]);
                uint32_t b1 = __float_as_uint(ws[ng][col + 4]);
                mma8(c[0][nt], A[0][kt], b0, b1);
                mma8(c[1][nt], A[1][kt], b0, b1);
            }
        }
        __syncthreads();
    }

    // epilogue: bias + store
    const float* biases[3] = {bk, bq, bv};
    #pragma unroll
    for (int nt = 0; nt < 12; ++nt) {
        const int ng0 = wn * 96 + nt * 8;
        const int p = ng0 >> 6;
        const int n = (ng0 & 63) + 2 * t;
        const float* __restrict__ bias = biases[p];
        const float b0 = bias[n], b1 = bias[n + 1];
        #pragma unroll
        for (int mt = 0; mt < 2; ++mt) {
            const int row = m0 + wm * 32 + mt * 16 + g;
            float2 lo = {c[mt][nt][0] + b0, c[mt][nt][1] + b1};
            float2 hi = {c[mt][nt][2] + b0, c[mt][nt][3] + b1};
            *(float2*)&g_kqv[p][row    ][n] = lo;
            *(float2*)&g_kqv[p][row + 8][n] = hi;
        }
    }
}

// ---------------------------------------------------------------------------
// Attention via mma.sync tf32.
// O[t] = sum_{s<=t} softplus((k_t . q_s)/32) * v_s
// 64x64 tiles; CTA handles t-blocks {i, 31-i}; grid (16, 8), single wave.
// Warp grid 4(m) x 2(n): warp computes 16 t-rows x 32 cols.
// smem stride 68 floats (68 mod 32 = 4 -> conflict-free fragment loads).
// ---------------------------------------------------------------------------
#define AST 68
#define ATTN_SMEM (4 * 64 * AST * 4)   // ks, qs, vT, Ps = 69632 B

__device__ __forceinline__ float softplus_f(float x) {
    return fmaxf(x, 0.f) + __logf(1.f + __expf(-fabsf(x)));
}

__global__ __launch_bounds__(256, 1) void attn_kernel(float* __restrict__ out)
{
    extern __shared__ float sm[];
    float* ks = sm;                 // [64][AST]  K tile [t][h]
    float* qs = sm + 64 * AST;      // [64][AST]  Q tile [s][h]
    float* vT = sm + 2 * 64 * AST;  // [64][AST]  V tile transposed [h][s]
    float* Ps = sm + 3 * 64 * AST;  // [64][AST]  P tile [t][s]

    const int b    = blockIdx.y;
    const int tid  = threadIdx.x;
    const int wid  = tid >> 5, lane = tid & 31;
    const int wm   = wid >> 1, wn = wid & 1;
    const int g    = lane >> 2, t = lane & 3;
    const int lr   = tid & 63;            // loader row
    const int lh   = (tid >> 6) * 4;      // loader col base

    const float* __restrict__ Kg = &g_kqv[0][(size_t)b * SEQ][0];
    const float* __restrict__ Qg = &g_kqv[1][(size_t)b * SEQ][0];
    const float* __restrict__ Vg = &g_kqv[2][(size_t)b * SEQ][0];

    for (int half = 0; half < 2; ++half) {
        const int tb = half ? (NTB - 1 - (int)blockIdx.x) : (int)blockIdx.x;

        // K tile [t][h], tf32-rounded
        #pragma unroll
        for (int i = 0; i < 4; ++i) {
            int idx = i * 256 + tid;
            int row = idx >> 4, hh = (idx & 15) * 4;
            float4 v = *(const float4*)&Kg[(size_t)(tb * 64 + row) * HEAD + hh];
            float* d = &ks[row * AST + hh];
            d[0] = to_tf32(v.x); d[1] = to_tf32(v.y); d[2] = to_tf32(v.z); d[3] = to_tf32(v.w);
        }
        __syncthreads();

        // K A-fragments: resident across whole s-loop. rows wm*16+g(+8), k-tiles over h
        uint32_t A[8][4];
        {
            const int row = wm * 16 + g;
            #pragma unroll
            for (int kt = 0; kt < 8; ++kt) {
                const int col = kt * 8 + t;
                A[kt][0] = __float_as_uint(ks[(row    ) * AST + col    ]);
                A[kt][1] = __float_as_uint(ks[(row + 8) * AST + col    ]);
                A[kt][2] = __float_as_uint(ks[(row    ) * AST + col + 4]);
                A[kt][3] = __float_as_uint(ks[(row + 8) * AST + col + 4]);
            }
        }

        float o[4][4];
        #pragma unroll
        for (int nt = 0; nt < 4; ++nt)
            #pragma unroll
            for (int r = 0; r < 4; ++r) o[nt][r] = 0.f;

        for (int sb = 0; sb <= tb; ++sb) {
            // Q tile [s][h]
            #pragma unroll
            for (int i = 0; i < 4; ++i) {
                int idx = i * 256 + tid;
                int row = idx >> 4, hh = (idx & 15) * 4;
                float4 v = *(const float4*)&Qg[(size_t)(sb * 64 + row) * HEAD + hh];
                float* d = &qs[row * AST + hh];
                d[0] = to_tf32(v.x); d[1] = to_tf32(v.y); d[2] = to_tf32(v.z); d[3] = to_tf32(v.w);
            }
            // V tile transposed [h][s]
            #pragma unroll
            for (int r = 0; r < 4; ++r) {
                int hh = lh + r * 16;
                float4 v = *(const float4*)&Vg[(size_t)(sb * 64 + lr) * HEAD + hh];
                vT[(hh + 0) * AST + lr] = to_tf32(v.x);
                vT[(hh + 1) * AST + lr] = to_tf32(v.y);
                vT[(hh + 2) * AST + lr] = to_tf32(v.z);
                vT[(hh + 3) * AST + lr] = to_tf32(v.w);
            }
            __syncthreads();

            // S = K . Q^T  (contract over h)
            float s_c[4][4];
            #pragma unroll
            for (int nt = 0; nt < 4; ++nt)
                #pragma unroll
                for (int r = 0; r < 4; ++r) s_c[nt][r] = 0.f;
            #pragma unroll
            for (int kt = 0; kt < 8; ++kt) {
                const int col = kt * 8 + t;
                #pragma unroll
                for (int nt = 0; nt < 4; ++nt) {
                    const int srow = wn * 32 + nt * 8 + g;
                    uint32_t b0 = __float_as_uint(qs[srow * AST + col    ]);
                    uint32_t b1 = __float_as_uint(qs[srow * AST + col + 4]);
                    mma8(s_c[nt], A[kt], b0, b1);
                }
            }

            // softplus + causal mask -> Ps [t][s]
            const bool diag = (sb == tb);
            const int trow = wm * 16 + g;
            #pragma unroll
            for (int nt = 0; nt < 4; ++nt) {
                const int sc = wn * 32 + nt * 8 + 2 * t;
                float p0 = softplus_f(s_c[nt][0] * 0.03125f);
                float p1 = softplus_f(s_c[nt][1] * 0.03125f);
                float p2 = softplus_f(s_c[nt][2] * 0.03125f);
                float p3 = softplus_f(s_c[nt][3] * 0.03125f);
                if (diag) {
                    if (sc     > trow    ) p0 = 0.f;
                    if (sc + 1 > trow    ) p1 = 0.f;
                    if (sc     > trow + 8) p2 = 0.f;
                    if (sc + 1 > trow + 8) p3 = 0.f;
                }
                *(float2*)&Ps[(trow    ) * AST + sc] = make_float2(p0, p1);
                *(float2*)&Ps[(trow + 8) * AST + sc] = make_float2(p2, p3);
            }
            __syncthreads();

            // O += P . V  (contract over s). A from Ps (tf32-round), B from vT.
            #pragma unroll
            for (int kt = 0; kt < 8; ++kt) {
                const int col = kt * 8 + t;
                uint32_t pa[4];
                pa[0] = to_tf32_bits(Ps[(trow    ) * AST + col    ]);
                pa[1] = to_tf32_bits(Ps[(trow + 8) * AST + col    ]);
                pa[2] = to_tf32_bits(Ps[(trow    ) * AST + col + 4]);
                pa[3] = to_tf32_bits(Ps[(trow + 8) * AST + col + 4]);
                #pragma unroll
                for (int nt = 0; nt < 4; ++nt) {
                    const int hrow = wn * 32 + nt * 8 + g;
                    uint32_t b0 = __float_as_uint(vT[hrow * AST + col    ]);
                    uint32_t b1 = __float_as_uint(vT[hrow * AST + col + 4]);
                    mma8(o[nt], pa, b0, b1);
                }
            }
            __syncthreads();
        }

        // write O tile
        {
            const size_t row0 = (size_t)b * SEQ + tb * 64 + wm * 16 + g;
            #pragma unroll
            for (int nt = 0; nt < 4; ++nt) {
                const int col = wn * 32 + nt * 8 + 2 * t;
                *(float2*)&out[(row0    ) * HEAD + col] = make_float2(o[nt][0], o[nt][1]);
                *(float2*)&out[(row0 + 8) * HEAD + col] = make_float2(o[nt][2], o[nt][3]);
            }
        }
        __syncthreads();   // before next half overwrites ks
    }
}

// ---------------------------------------------------------------------------
extern "C" void kernel_launch(void* const* d_in, const int* in_sizes, int n_in,
                              void* d_out, int out_size)
{
    const float* x  = (const float*)d_in[0];
    const float* Wk = (const float*)d_in[1];
    const float* bk = (const float*)d_in[2];
    const float* Wq = (const float*)d_in[3];
    const float* bq = (const float*)d_in[4];
    const float* Wv = (const float*)d_in[5];
    const float* bv = (const float*)d_in[6];
    float* out = (float*)d_out;

    static int init = 0;
    if (!init) {
        cudaFuncSetAttribute(attn_kernel, cudaFuncAttributeMaxDynamicSharedMemorySize, ATTN_SMEM);
        init = 1;
    }

    dim3 wg(NEMB / 64, 3);
    wt_kernel<<<wg, 256>>>(Wk, Wq, Wv);

    proj_mma_kernel<<<MTOT / 128, 256>>>(x, bk, bq, bv);

    dim3 ag(NTB / 2, BATCH);
    attn_kernel<<<ag, 256, ATTN_SMEM>>>(out);
}

// round 7
// speedup vs baseline: 3.0430x; 1.1522x over previous
#include <cuda_runtime.h>
#include <cstdint>
#include <math.h>

#define HEAD 64
#define NEMB 1024
#define BATCH 8
#define SEQ   2048
#define MTOT  (BATCH*SEQ)   // 16384
#define NTB   (SEQ/64)      // 32 t-blocks per batch

// scratch: projected k,q,v fp32 (12.6 MB) + transposed tf32-rounded weights
__device__ float g_kqv[3][MTOT][HEAD];
__device__ float g_Wt[3][HEAD][NEMB];   // Wt[p][n][k] = rna_tf32(W[p][k][n])

__device__ __forceinline__ float to_tf32(float x) {
    float y; asm("cvt.rna.tf32.f32 %0, %1;" : "=f"(y) : "f"(x)); return y;
}
__device__ __forceinline__ uint32_t to_tf32_bits(float x) {
    float y; asm("cvt.rna.tf32.f32 %0, %1;" : "=f"(y) : "f"(x));
    return __float_as_uint(y);
}

// D += A*B : m16n8k8 tf32 (A row-major frag, B col-major frag), fp32 accum
__device__ __forceinline__ void mma8(float c[4], const uint32_t a[4], uint32_t b0, uint32_t b1) {
    asm volatile(
        "mma.sync.aligned.m16n8k8.row.col.f32.tf32.tf32.f32 "
        "{%0,%1,%2,%3}, {%4,%5,%6,%7}, {%8,%9}, {%0,%1,%2,%3};"
        : "+f"(c[0]), "+f"(c[1]), "+f"(c[2]), "+f"(c[3])
        : "r"(a[0]), "r"(a[1]), "r"(a[2]), "r"(a[3]), "r"(b0), "r"(b1));
}

// ---------------------------------------------------------------------------
// W transpose + tf32 pre-round via smem tile (coalesced both ways):
//   g_Wt[p][n][k] = rna(W[p][k][n])
// grid (16, 3): each block transposes a 64(k) x 64(n) tile.
// ---------------------------------------------------------------------------
__global__ __launch_bounds__(256) void wt_kernel(
    const float* __restrict__ Wk, const float* __restrict__ Wq, const float* __restrict__ Wv)
{
    __shared__ float t[64][65];
    const float* __restrict__ W = (blockIdx.y == 0) ? Wk : ((blockIdx.y == 1) ? Wq : Wv);
    const int k0 = blockIdx.x * 64;
    const int tid = threadIdx.x;
    #pragma unroll
    for (int i = 0; i < 16; ++i) {
        int idx = i * 256 + tid;          // 0..4095
        int kk = idx >> 6, n = idx & 63;  // consecutive tid -> consecutive n (coalesced read)
        t[n][kk] = to_tf32(W[(size_t)(k0 + kk) * HEAD + n]);
    }
    __syncthreads();
    #pragma unroll
    for (int i = 0; i < 16; ++i) {
        int idx = i * 256 + tid;
        int n = idx >> 6, kk = idx & 63;  // consecutive tid -> consecutive k (coalesced write)
        g_Wt[blockIdx.y][n][k0 + kk] = t[n][kk];
    }
}

// ---------------------------------------------------------------------------
// Projection via mma.sync tf32. CTA tile: 128(m) x 192(n=3x64), K chunk 32.
// 8 warps in 4(m) x 2(n) grid. smem stride 36 (conflict-free fragment loads).
// Software-pipelined: LDGs for chunk ch+1 issued before MMA of chunk ch.
// ---------------------------------------------------------------------------
__global__ __launch_bounds__(256, 1) void proj_mma_kernel(
    const float* __restrict__ x,
    const float* __restrict__ bk, const float* __restrict__ bq, const float* __restrict__ bv)
{
    __shared__ float xs[128][36];   // [m][k] tf32-rounded
    __shared__ float ws[192][36];   // [n_global][k] tf32-rounded

    const int tid  = threadIdx.x;
    const int wid  = tid >> 5, lane = tid & 31;
    const int wm   = wid >> 1, wn = wid & 1;
    const int g    = lane >> 2, t = lane & 3;
    const int m0   = blockIdx.x * 128;

    // loader indices (fixed per thread)
    int xrow[4], xcol[4], wrow[6], wcol[6];
    #pragma unroll
    for (int i = 0; i < 4; ++i) { int idx = i * 256 + tid; xrow[i] = idx >> 3; xcol[i] = (idx & 7) * 4; }
    #pragma unroll
    for (int i = 0; i < 6; ++i) { int idx = i * 256 + tid; wrow[i] = idx >> 3; wcol[i] = (idx & 7) * 4; }

    float c[2][12][4];
    #pragma unroll
    for (int mt = 0; mt < 2; ++mt)
        #pragma unroll
        for (int nt = 0; nt < 12; ++nt)
            #pragma unroll
            for (int r = 0; r < 4; ++r) c[mt][nt][r] = 0.f;

    float4 xr[4], wr[6];

    // prologue: load chunk 0
    #pragma unroll
    for (int i = 0; i < 4; ++i)
        xr[i] = *(const float4*)&x[(size_t)(m0 + xrow[i]) * NEMB + xcol[i]];
    #pragma unroll
    for (int i = 0; i < 6; ++i)
        wr[i] = *(const float4*)&g_Wt[wrow[i] >> 6][wrow[i] & 63][wcol[i]];
    #pragma unroll
    for (int i = 0; i < 4; ++i) {
        float* d = &xs[xrow[i]][xcol[i]];
        d[0] = to_tf32(xr[i].x); d[1] = to_tf32(xr[i].y); d[2] = to_tf32(xr[i].z); d[3] = to_tf32(xr[i].w);
    }
    #pragma unroll
    for (int i = 0; i < 6; ++i)
        *(float4*)&ws[wrow[i]][wcol[i]] = wr[i];
    __syncthreads();

    for (int ch = 0; ch < 32; ++ch) {
        // prefetch next chunk into registers (overlaps with MMA below)
        if (ch < 31) {
            const int k1 = (ch + 1) * 32;
            #pragma unroll
            for (int i = 0; i < 4; ++i)
                xr[i] = *(const float4*)&x[(size_t)(m0 + xrow[i]) * NEMB + k1 + xcol[i]];
            #pragma unroll
            for (int i = 0; i < 6; ++i)
                wr[i] = *(const float4*)&g_Wt[wrow[i] >> 6][wrow[i] & 63][k1 + wcol[i]];
        }

        // A fragments: 2 m-tiles x 4 k-tiles
        uint32_t A[2][4][4];
        #pragma unroll
        for (int mt = 0; mt < 2; ++mt) {
            const int row = wm * 32 + mt * 16 + g;
            #pragma unroll
            for (int kt = 0; kt < 4; ++kt) {
                const int col = kt * 8 + t;
                A[mt][kt][0] = __float_as_uint(xs[row    ][col    ]);
                A[mt][kt][1] = __float_as_uint(xs[row + 8][col    ]);
                A[mt][kt][2] = __float_as_uint(xs[row    ][col + 4]);
                A[mt][kt][3] = __float_as_uint(xs[row + 8][col + 4]);
            }
        }
        #pragma unroll
        for (int kt = 0; kt < 4; ++kt) {
            #pragma unroll
            for (int nt = 0; nt < 12; ++nt) {
                const int ng = wn * 96 + nt * 8 + g;
                const int col = kt * 8 + t;
                uint32_t b0 = __float_as_uint(ws[ng][col]);
                uint32_t b1 = __float_as_uint(ws[ng][col + 4]);
                mma8(c[0][nt], A[0][kt], b0, b1);
                mma8(c[1][nt], A[1][kt], b0, b1);
            }
        }
        __syncthreads();      // all smem reads of this chunk done

        if (ch < 31) {
            #pragma unroll
            for (int i = 0; i < 4; ++i) {
                float* d = &xs[xrow[i]][xcol[i]];
                d[0] = to_tf32(xr[i].x); d[1] = to_tf32(xr[i].y);
                d[2] = to_tf32(xr[i].z); d[3] = to_tf32(xr[i].w);
            }
            #pragma unroll
            for (int i = 0; i < 6; ++i)
                *(float4*)&ws[wrow[i]][wcol[i]] = wr[i];
            __syncthreads();  // stores visible before next chunk's MMA
        }
    }

    // epilogue: bias + store
    const float* biases[3] = {bk, bq, bv};
    #pragma unroll
    for (int nt = 0; nt < 12; ++nt) {
        const int ng0 = wn * 96 + nt * 8;
        const int p = ng0 >> 6;
        const int n = (ng0 & 63) + 2 * t;
        const float* __restrict__ bias = biases[p];
        const float b0 = bias[n], b1 = bias[n + 1];
        #pragma unroll
        for (int mt = 0; mt < 2; ++mt) {
            const int row = m0 + wm * 32 + mt * 16 + g;
            float2 lo = {c[mt][nt][0] + b0, c[mt][nt][1] + b1};
            float2 hi = {c[mt][nt][2] + b0, c[mt][nt][3] + b1};
            *(float2*)&g_kqv[p][row    ][n] = lo;
            *(float2*)&g_kqv[p][row + 8][n] = hi;
        }
    }
}

// ---------------------------------------------------------------------------
// Attention via mma.sync tf32, software-pipelined Q/V loads.
// O[t] = sum_{s<=t} softplus((k_t . q_s)/32) * v_s
// 64x64 tiles; CTA handles t-blocks {i, 31-i}; grid (16, 8), single wave.
// ---------------------------------------------------------------------------
#define AST 68
#define ATTN_SMEM (4 * 64 * AST * 4)   // ks, qs, vT, Ps = 69632 B

__device__ __forceinline__ float softplus_f(float x) {
    return fmaxf(x, 0.f) + __logf(1.f + __expf(-fabsf(x)));
}

__global__ __launch_bounds__(256, 1) void attn_kernel(float* __restrict__ out)
{
    extern __shared__ float sm[];
    float* ks = sm;                 // [64][AST]  K tile [t][h]
    float* qs = sm + 64 * AST;      // [64][AST]  Q tile [s][h]
    float* vT = sm + 2 * 64 * AST;  // [64][AST]  V tile transposed [h][s]
    float* Ps = sm + 3 * 64 * AST;  // [64][AST]  P tile [t][s]

    const int b    = blockIdx.y;
    const int tid  = threadIdx.x;
    const int wid  = tid >> 5, lane = tid & 31;
    const int wm   = wid >> 1, wn = wid & 1;
    const int g    = lane >> 2, t = lane & 3;
    const int lr   = tid & 63;            // loader row
    const int lh   = (tid >> 6) * 4;      // loader col base

    // fixed loader indices for Q ([s][h] layout)
    int qrow[4], qcol[4];
    #pragma unroll
    for (int i = 0; i < 4; ++i) { int idx = i * 256 + tid; qrow[i] = idx >> 4; qcol[i] = (idx & 15) * 4; }

    const float* __restrict__ Kg = &g_kqv[0][(size_t)b * SEQ][0];
    const float* __restrict__ Qg = &g_kqv[1][(size_t)b * SEQ][0];
    const float* __restrict__ Vg = &g_kqv[2][(size_t)b * SEQ][0];

    for (int half = 0; half < 2; ++half) {
        const int tb = half ? (NTB - 1 - (int)blockIdx.x) : (int)blockIdx.x;

        // K tile [t][h], tf32-rounded
        #pragma unroll
        for (int i = 0; i < 4; ++i) {
            float4 v = *(const float4*)&Kg[(size_t)(tb * 64 + qrow[i]) * HEAD + qcol[i]];
            float* d = &ks[qrow[i] * AST + qcol[i]];
            d[0] = to_tf32(v.x); d[1] = to_tf32(v.y); d[2] = to_tf32(v.z); d[3] = to_tf32(v.w);
        }
        __syncthreads();

        // K A-fragments: resident across whole s-loop
        uint32_t A[8][4];
        const int trow = wm * 16 + g;
        #pragma unroll
        for (int kt = 0; kt < 8; ++kt) {
            const int col = kt * 8 + t;
            A[kt][0] = __float_as_uint(ks[(trow    ) * AST + col    ]);
            A[kt][1] = __float_as_uint(ks[(trow + 8) * AST + col    ]);
            A[kt][2] = __float_as_uint(ks[(trow    ) * AST + col + 4]);
            A[kt][3] = __float_as_uint(ks[(trow + 8) * AST + col + 4]);
        }

        float o[4][4];
        #pragma unroll
        for (int nt = 0; nt < 4; ++nt)
            #pragma unroll
            for (int r = 0; r < 4; ++r) o[nt][r] = 0.f;

        // prologue: load sb=0 tiles into smem
        float4 qr[4], vr[4];
        #pragma unroll
        for (int i = 0; i < 4; ++i)
            qr[i] = *(const float4*)&Qg[(size_t)qrow[i] * HEAD + qcol[i]];
        #pragma unroll
        for (int r = 0; r < 4; ++r)
            vr[r] = *(const float4*)&Vg[(size_t)lr * HEAD + (lh + r * 16)];
        #pragma unroll
        for (int i = 0; i < 4; ++i) {
            float* d = &qs[qrow[i] * AST + qcol[i]];
            d[0] = to_tf32(qr[i].x); d[1] = to_tf32(qr[i].y); d[2] = to_tf32(qr[i].z); d[3] = to_tf32(qr[i].w);
        }
        #pragma unroll
        for (int r = 0; r < 4; ++r) {
            int hh = lh + r * 16;
            vT[(hh + 0) * AST + lr] = to_tf32(vr[r].x);
            vT[(hh + 1) * AST + lr] = to_tf32(vr[r].y);
            vT[(hh + 2) * AST + lr] = to_tf32(vr[r].z);
            vT[(hh + 3) * AST + lr] = to_tf32(vr[r].w);
        }
        __syncthreads();

        for (int sb = 0; sb <= tb; ++sb) {
            // prefetch next tiles into registers (overlaps S-phase + O-phase)
            if (sb < tb) {
                const size_t s1 = (size_t)(sb + 1) * 64;
                #pragma unroll
                for (int i = 0; i < 4; ++i)
                    qr[i] = *(const float4*)&Qg[(s1 + qrow[i]) * HEAD + qcol[i]];
                #pragma unroll
                for (int r = 0; r < 4; ++r)
                    vr[r] = *(const float4*)&Vg[(s1 + lr) * HEAD + (lh + r * 16)];
            }

            // S = K . Q^T  (contract over h)
            float s_c[4][4];
            #pragma unroll
            for (int nt = 0; nt < 4; ++nt)
                #pragma unroll
                for (int r = 0; r < 4; ++r) s_c[nt][r] = 0.f;
            #pragma unroll
            for (int kt = 0; kt < 8; ++kt) {
                const int col = kt * 8 + t;
                #pragma unroll
                for (int nt = 0; nt < 4; ++nt) {
                    const int srow = wn * 32 + nt * 8 + g;
                    uint32_t b0 = __float_as_uint(qs[srow * AST + col    ]);
                    uint32_t b1 = __float_as_uint(qs[srow * AST + col + 4]);
                    mma8(s_c[nt], A[kt], b0, b1);
                }
            }

            // softplus + causal mask -> Ps [t][s]
            const bool diag = (sb == tb);
            #pragma unroll
            for (int nt = 0; nt < 4; ++nt) {
                const int sc = wn * 32 + nt * 8 + 2 * t;
                float p0 = softplus_f(s_c[nt][0] * 0.03125f);
                float p1 = softplus_f(s_c[nt][1] * 0.03125f);
                float p2 = softplus_f(s_c[nt][2] * 0.03125f);
                float p3 = softplus_f(s_c[nt][3] * 0.03125f);
                if (diag) {
                    if (sc     > trow    ) p0 = 0.f;
                    if (sc + 1 > trow    ) p1 = 0.f;
                    if (sc     > trow + 8) p2 = 0.f;
                    if (sc + 1 > trow + 8) p3 = 0.f;
                }
                *(float2*)&Ps[(trow    ) * AST + sc] = make_float2(p0, p1);
                *(float2*)&Ps[(trow + 8) * AST + sc] = make_float2(p2, p3);
            }
            __syncthreads();   // Ps visible to all warps

            // O += P . V  (contract over s)
            #pragma unroll
            for (int kt = 0; kt < 8; ++kt) {
                const int col = kt * 8 + t;
                uint32_t pa[4];
                pa[0] = to_tf32_bits(Ps[(trow    ) * AST + col    ]);
                pa[1] = to_tf32_bits(Ps[(trow + 8) * AST + col    ]);
                pa[2] = to_tf32_bits(Ps[(trow    ) * AST + col + 4]);
                pa[3] = to_tf32_bits(Ps[(trow + 8) * AST + col + 4]);
                #pragma unroll
                for (int nt = 0; nt < 4; ++nt) {
                    const int hrow = wn * 32 + nt * 8 + g;
                    uint32_t b0 = __float_as_uint(vT[hrow * AST + col    ]);
                    uint32_t b1 = __float_as_uint(vT[hrow * AST + col + 4]);
                    mma8(o[nt], pa, b0, b1);
                }
            }
            __syncthreads();   // all reads of qs/vT done

            if (sb < tb) {
                #pragma unroll
                for (int i = 0; i < 4; ++i) {
                    float* d = &qs[qrow[i] * AST + qcol[i]];
                    d[0] = to_tf32(qr[i].x); d[1] = to_tf32(qr[i].y);
                    d[2] = to_tf32(qr[i].z); d[3] = to_tf32(qr[i].w);
                }
                #pragma unroll
                for (int r = 0; r < 4; ++r) {
                    int hh = lh + r * 16;
                    vT[(hh + 0) * AST + lr] = to_tf32(vr[r].x);
                    vT[(hh + 1) * AST + lr] = to_tf32(vr[r].y);
                    vT[(hh + 2) * AST + lr] = to_tf32(vr[r].z);
                    vT[(hh + 3) * AST + lr] = to_tf32(vr[r].w);
                }
                __syncthreads();  // stores visible before next S-MMA
            }
        }

        // write O tile
        {
            const size_t row0 = (size_t)b * SEQ + tb * 64 + trow;
            #pragma unroll
            for (int nt = 0; nt < 4; ++nt) {
                const int col = wn * 32 + nt * 8 + 2 * t;
                *(float2*)&out[(row0    ) * HEAD + col] = make_float2(o[nt][0], o[nt][1]);
                *(float2*)&out[(row0 + 8) * HEAD + col] = make_float2(o[nt][2], o[nt][3]);
            }
        }
        __syncthreads();   // before next half overwrites ks/qs/vT
    }
}

// ---------------------------------------------------------------------------
extern "C" void kernel_launch(void* const* d_in, const int* in_sizes, int n_in,
                              void* d_out, int out_size)
{
    const float* x  = (const float*)d_in[0];
    const float* Wk = (const float*)d_in[1];
    const float* bk = (const float*)d_in[2];
    const float* Wq = (const float*)d_in[3];
    const float* bq = (const float*)d_in[4];
    const float* Wv = (const float*)d_in[5];
    const float* bv = (const float*)d_in[6];
    float* out = (float*)d_out;

    static int init = 0;
    if (!init) {
        cudaFuncSetAttribute(attn_kernel, cudaFuncAttributeMaxDynamicSharedMemorySize, ATTN_SMEM);
        init = 1;
    }

    dim3 wg(NEMB / 64, 3);
    wt_kernel<<<wg, 256>>>(Wk, Wq, Wv);

    proj_mma_kernel<<<MTOT / 128, 256>>>(x, bk, bq, bv);

    dim3 ag(NTB / 2, BATCH);
    attn_kernel<<<ag, 256, ATTN_SMEM>>>(out);
}